// round 6
// baseline (speedup 1.0000x reference)
#include <cuda_runtime.h>
#include <cuda_bf16.h>
#include <cstdint>

#define BATCH 16
#define NPTS  4096
#define CIN   64
#define NSAMP 1024
#define KNBR  32
#define FULLM 0xffffffffu

// ---------------- f32x2 helpers (FPS only) ----------------
#define PACKF2(d, lo, hi)  asm("mov.b64 %0, {%1, %2};" : "=l"(d) : "f"(lo), "f"(hi))
#define UNPACKF2(lo, hi, s) asm("mov.b64 {%0, %1}, %2;" : "=f"(lo), "=f"(hi) : "l"(s))
#define ADD2(d, a, b) asm("add.rn.f32x2 %0, %1, %2;" : "=l"(d) : "l"(a), "l"(b))
#define MUL2(d, a, b) asm("mul.rn.f32x2 %0, %1, %2;" : "=l"(d) : "l"(a), "l"(b))

__device__ int d_ball[BATCH * NSAMP * KNBR];

#define AMAX(vA, jA, vB, jB, vO, jO) { bool g_ = ((vB) > (vA)); (vO) = g_ ? (vB) : (vA); (jO) = g_ ? (jB) : (jA); }

// ---------------------------------------------------------------------------
// Kernel 1: FPS. xyz in shared as float4 (1 LDS.128 per centroid read),
// cross-warp argmax via 64-bit shared atomicMax on a ping-pong slot.
// ---------------------------------------------------------------------------
__global__ __launch_bounds__(256) void fps_kernel(const float* __restrict__ xyz,
                                                  float* __restrict__ new_xyz)
{
    extern __shared__ float sm[];
    float4* sxyz = (float4*)sm;                               // 4096 * 16B
    unsigned long long* sred = (unsigned long long*)(sm + NPTS * 4);  // [2]

    const int b = blockIdx.x, tid = threadIdx.x;
    const int lane = tid & 31;
    const float* gx = xyz + (size_t)b * NPTS * 3;

    for (int i = tid; i < NPTS; i += 256) {
        float4 v;
        v.x = gx[3 * i]; v.y = gx[3 * i + 1]; v.z = gx[3 * i + 2]; v.w = 0.f;
        sxyz[i] = v;
    }
    if (tid < 2) sred[tid] = 0ull;
    __syncthreads();

    // register-resident points: slot j -> global index tid + j*256 (increasing)
    unsigned long long px[8], py[8], pz[8];
    float dist[16];
#pragma unroll
    for (int q = 0; q < 8; q++) {
        float4 a = sxyz[tid + (2 * q) * 256];
        float4 c = sxyz[tid + (2 * q + 1) * 256];
        PACKF2(px[q], a.x, c.x);
        PACKF2(py[q], a.y, c.y);
        PACKF2(pz[q], a.z, c.z);
        dist[2 * q] = 1e10f; dist[2 * q + 1] = 1e10f;
    }

    int far = 0;
    for (int t = 0; t < NSAMP; t++) {
        float4 cen = sxyz[far];
        if (tid == 0) {
            float* o = new_xyz + ((size_t)b * NSAMP + t) * 3;
            o[0] = cen.x; o[1] = cen.y; o[2] = cen.z;
            sred[(t + 1) & 1] = 0ull;        // reset next slot before the bar
        }
        unsigned long long ncx, ncy, ncz;
        float mx = -cen.x, my = -cen.y, mz = -cen.z;
        PACKF2(ncx, mx, mx); PACKF2(ncy, my, my); PACKF2(ncz, mz, mz);

        float v[16];
#pragma unroll
        for (int q = 0; q < 8; q++) {
            unsigned long long dx, dy, dz, xx, yy, zz, s, d2;
            ADD2(dx, px[q], ncx);                 // p + (-c) == p - c exactly
            ADD2(dy, py[q], ncy);
            ADD2(dz, pz[q], ncz);
            MUL2(xx, dx, dx); MUL2(yy, dy, dy); MUL2(zz, dz, dz);
            ADD2(s, xx, yy); ADD2(d2, s, zz);     // (x²+y²)+z² order
            float d0, d1;
            UNPACKF2(d0, d1, d2);
            float n0 = fminf(dist[2 * q], d0);     dist[2 * q] = n0;     v[2 * q] = n0;
            float n1 = fminf(dist[2 * q + 1], d1); dist[2 * q + 1] = n1; v[2 * q + 1] = n1;
        }
        // tree argmax over 16 slots (min slot on ties -> min index)
        float va[8]; int ja[8];
#pragma unroll
        for (int q = 0; q < 8; q++) AMAX(v[2 * q], 2 * q, v[2 * q + 1], 2 * q + 1, va[q], ja[q]);
        float vb[4]; int jb[4];
#pragma unroll
        for (int q = 0; q < 4; q++) AMAX(va[2 * q], ja[2 * q], va[2 * q + 1], ja[2 * q + 1], vb[q], jb[q]);
        float vc0, vc1; int jc0, jc1;
        AMAX(vb[0], jb[0], vb[1], jb[1], vc0, jc0);
        AMAX(vb[2], jb[2], vb[3], jb[3], vc1, jc1);
        float mv; int mj;
        AMAX(vc0, jc0, vc1, jc1, mv, mj);
        int bi = tid + mj * 256;

        // warp argmax: REDUX max bits; among equals keep max(4095-idx) = min idx
        unsigned bits = __float_as_uint(mv);
        unsigned wmax = __reduce_max_sync(FULLM, bits);
        unsigned cand = (bits == wmax) ? (unsigned)(4095 - bi) : 0u;
        unsigned winv = __reduce_max_sync(FULLM, cand);

        if (lane == 0)
            atomicMax(&sred[t & 1], ((unsigned long long)wmax << 32) | winv);
        __syncthreads();
        unsigned long long key = sred[t & 1];
        far = 4095 - (int)(unsigned)(key & 0xffffffffull);
    }
}

// ---------------------------------------------------------------------------
// Kernel 2: ball query (unchanged)
// ---------------------------------------------------------------------------
__global__ __launch_bounds__(256) void query_kernel(const float* __restrict__ xyz,
                                                    const float* __restrict__ new_xyz)
{
    const int warp = threadIdx.x >> 5, lane = threadIdx.x & 31;
    const int gs = blockIdx.x * 8 + warp;
    const int b  = gs >> 10;
    const float* nc = new_xyz + (size_t)gs * 3;
    const float cx = nc[0], cy = nc[1], cz = nc[2];
    const float* gx = xyz + (size_t)b * NPTS * 3;
    int* out = d_ball + (size_t)gs * KNBR;
    const float R2 = 0.04f;

    int cnt = 0, first = -1;
    for (int base = 0; base < NPTS && cnt < KNBR; base += 32) {
        int j = base + lane;
        float dx = __fsub_rn(cx, gx[3 * j]);
        float dy = __fsub_rn(cy, gx[3 * j + 1]);
        float dz = __fsub_rn(cz, gx[3 * j + 2]);
        float d2 = __fadd_rn(__fadd_rn(__fmul_rn(dx, dx), __fmul_rn(dy, dy)),
                             __fmul_rn(dz, dz));
        bool in = (d2 <= R2);
        unsigned m = __ballot_sync(FULLM, in);
        int pos = cnt + __popc(m & ((1u << lane) - 1u));
        if (in && pos < KNBR) {
            out[pos] = j;
            if (pos == 0) first = j;
        }
        cnt += __popc(m);
    }
    unsigned hf = __ballot_sync(FULLM, first >= 0);
    int src = __ffs(hf) - 1;
    first = __shfl_sync(FULLM, first, src);
    int filled = cnt < KNBR ? cnt : KNBR;
    if (lane >= filled) out[lane] = first;
}

// ---------------------------------------------------------------------------
// Kernel 3: MLP via mma.sync (m16n8k16 bf16, 3-term hi/mid split).
// B fragments loaded pairwise via ldmatrix.x4 (halved B-ldsm count).
// ---------------------------------------------------------------------------
#define ASTRIDE  176
#define WSTR1    176
#define WSTR23   144
#define SM_BIAS  0
#define SM_W1H   1024
#define SM_W1M   12288
#define SM_W2H   23552
#define SM_W2M   32768
#define SM_W3H   41984
#define SM_W3M   60416
#define SM_ACT   78848
#define ACTW     11264
#define SM_MLP_END (78848 + 8 * ACTW)   // 168960

__device__ __forceinline__ unsigned pk_hi(float a, float b) {
    __nv_bfloat16 ha = __float2bfloat16_rn(a), hb = __float2bfloat16_rn(b);
    return ((unsigned)__bfloat16_as_ushort(hb) << 16) | __bfloat16_as_ushort(ha);
}
__device__ __forceinline__ unsigned pk_mid(float a, float b) {
    __nv_bfloat16 ha = __float2bfloat16_rn(a), hb = __float2bfloat16_rn(b);
    __nv_bfloat16 ma = __float2bfloat16_rn(a - __bfloat162float(ha));
    __nv_bfloat16 mb = __float2bfloat16_rn(b - __bfloat162float(hb));
    return ((unsigned)__bfloat16_as_ushort(mb) << 16) | __bfloat16_as_ushort(ma);
}
__device__ __forceinline__ uint32_t smem_u32(const void* p) {
    uint32_t a;
    asm("{ .reg .u64 t; cvta.to.shared.u64 t, %1; cvt.u32.u64 %0, t; }" : "=r"(a) : "l"(p));
    return a;
}
__device__ __forceinline__ void ldsm4(uint32_t* r, uint32_t addr) {
    asm volatile("ldmatrix.sync.aligned.m8n8.x4.shared.b16 {%0,%1,%2,%3}, [%4];"
        : "=r"(r[0]), "=r"(r[1]), "=r"(r[2]), "=r"(r[3]) : "r"(addr));
}
__device__ __forceinline__ void mma_bf16(float* d, const uint32_t* a, uint32_t b0, uint32_t b1) {
    asm volatile("mma.sync.aligned.m16n8k16.row.col.f32.bf16.bf16.f32 "
        "{%0,%1,%2,%3}, {%4,%5,%6,%7}, {%8,%9}, {%0,%1,%2,%3};"
        : "+f"(d[0]), "+f"(d[1]), "+f"(d[2]), "+f"(d[3])
        : "r"(a[0]), "r"(a[1]), "r"(a[2]), "r"(a[3]), "r"(b0), "r"(b1));
}

template<int KT, int WSTR>
__device__ __forceinline__ void run_layer(uint32_t aH, uint32_t aM,
                                          uint32_t wHb, uint32_t wMb,
                                          float acc[2][8][4])
{
#pragma unroll
    for (int m = 0; m < 2; m++)
#pragma unroll
        for (int n = 0; n < 8; n++)
#pragma unroll
            for (int q = 0; q < 4; q++) acc[m][n][q] = 0.f;
#pragma unroll
    for (int k = 0; k < KT; k++) {
        uint32_t ah[2][4], am[2][4];
        ldsm4(ah[0], aH + k * 32);
        ldsm4(ah[1], aH + 16 * ASTRIDE + k * 32);
        ldsm4(am[0], aM + k * 32);
        ldsm4(am[1], aM + 16 * ASTRIDE + k * 32);
#pragma unroll
        for (int np = 0; np < 4; np++) {
            // x4 over 16 B-rows: {r0,r2} = n-tile 2*np, {r1,r3} = n-tile 2*np+1
            uint32_t bh[4], bm[4];
            ldsm4(bh, wHb + (np * 16) * WSTR + k * 32);
            ldsm4(bm, wMb + (np * 16) * WSTR + k * 32);
#pragma unroll
            for (int m = 0; m < 2; m++) {
                mma_bf16(acc[m][2 * np],     ah[m], bh[0], bh[2]);
                mma_bf16(acc[m][2 * np],     am[m], bh[0], bh[2]);
                mma_bf16(acc[m][2 * np],     ah[m], bm[0], bm[2]);
                mma_bf16(acc[m][2 * np + 1], ah[m], bh[1], bh[3]);
                mma_bf16(acc[m][2 * np + 1], am[m], bh[1], bh[3]);
                mma_bf16(acc[m][2 * np + 1], ah[m], bm[1], bm[3]);
            }
        }
    }
}

__device__ __forceinline__ void epi_store(float acc[2][8][4],
    char* actH, char* actM, const float* bias, int lane)
{
    const int cg = lane & 3, rg = lane >> 2;
#pragma unroll
    for (int m = 0; m < 2; m++) {
#pragma unroll
        for (int n = 0; n < 8; n++) {
            int n0 = n * 8 + 2 * cg;
            float b0v = bias[n0], b1v = bias[n0 + 1];
            float x0 = fmaxf(acc[m][n][0] + b0v, 0.f);
            float x1 = fmaxf(acc[m][n][1] + b1v, 0.f);
            float x2 = fmaxf(acc[m][n][2] + b0v, 0.f);
            float x3 = fmaxf(acc[m][n][3] + b1v, 0.f);
            int r0 = m * 16 + rg, r1 = r0 + 8;
            *(uint32_t*)(actH + r0 * ASTRIDE + n0 * 2) = pk_hi(x0, x1);
            *(uint32_t*)(actH + r1 * ASTRIDE + n0 * 2) = pk_hi(x2, x3);
            *(uint32_t*)(actM + r0 * ASTRIDE + n0 * 2) = pk_mid(x0, x1);
            *(uint32_t*)(actM + r1 * ASTRIDE + n0 * 2) = pk_mid(x2, x3);
        }
    }
}

__device__ __forceinline__ void epi_max(float acc[2][8][4], const float* bias,
                                        float* outp, int nbase, int lane)
{
    const int cg = lane & 3;
#pragma unroll
    for (int n = 0; n < 8; n++) {
        int n0 = nbase + n * 8 + 2 * cg;
        float b0v = bias[n0], b1v = bias[n0 + 1];
        float v0 = fmaxf(fmaxf(acc[0][n][0] + b0v, 0.f), fmaxf(acc[0][n][2] + b0v, 0.f));
        v0 = fmaxf(v0, fmaxf(fmaxf(acc[1][n][0] + b0v, 0.f), fmaxf(acc[1][n][2] + b0v, 0.f)));
        float v1 = fmaxf(fmaxf(acc[0][n][1] + b1v, 0.f), fmaxf(acc[0][n][3] + b1v, 0.f));
        v1 = fmaxf(v1, fmaxf(fmaxf(acc[1][n][1] + b1v, 0.f), fmaxf(acc[1][n][3] + b1v, 0.f)));
#pragma unroll
        for (int o = 4; o <= 16; o <<= 1) {
            v0 = fmaxf(v0, __shfl_xor_sync(FULLM, v0, o));
            v1 = fmaxf(v1, __shfl_xor_sync(FULLM, v1, o));
        }
        if (lane < 4) { outp[n0] = v0; outp[n0 + 1] = v1; }
    }
}

__global__ __launch_bounds__(256) void mlp_kernel(
    const float* __restrict__ xyz, const float* __restrict__ pts,
    const float* __restrict__ w0, const float* __restrict__ b0,
    const float* __restrict__ w1, const float* __restrict__ b1,
    const float* __restrict__ w2, const float* __restrict__ b2,
    const float* __restrict__ new_xyz, float* __restrict__ new_points)
{
    extern __shared__ char smem[];
    const uint32_t sb = smem_u32(smem);
    const int tid = threadIdx.x, wid = tid >> 5, lane = tid & 31;

    float* b0s = (float*)(smem + SM_BIAS);
    float* b1s = b0s + 64;
    float* b2s = b1s + 64;
    if (tid < 64) { b0s[tid] = b0[tid]; b1s[tid] = b1[tid]; }
    if (tid < 128) b2s[tid] = b2[tid];

    for (int idx = tid; idx < 64 * 80; idx += 256) {
        int n = idx / 80, k = idx - n * 80;
        float w = (k < 67) ? w0[k * 64 + n] : 0.f;
        __nv_bfloat16 h = __float2bfloat16_rn(w);
        __nv_bfloat16 m = __float2bfloat16_rn(w - __bfloat162float(h));
        *(unsigned short*)(smem + SM_W1H + n * WSTR1 + k * 2) = __bfloat16_as_ushort(h);
        *(unsigned short*)(smem + SM_W1M + n * WSTR1 + k * 2) = __bfloat16_as_ushort(m);
    }
    for (int idx = tid; idx < 64 * 64; idx += 256) {
        int n = idx >> 6, k = idx & 63;
        float w = w1[k * 64 + n];
        __nv_bfloat16 h = __float2bfloat16_rn(w);
        __nv_bfloat16 m = __float2bfloat16_rn(w - __bfloat162float(h));
        *(unsigned short*)(smem + SM_W2H + n * WSTR23 + k * 2) = __bfloat16_as_ushort(h);
        *(unsigned short*)(smem + SM_W2M + n * WSTR23 + k * 2) = __bfloat16_as_ushort(m);
    }
    for (int idx = tid; idx < 128 * 64; idx += 256) {
        int n = idx >> 6, k = idx & 63;
        float w = w2[k * 128 + n];
        __nv_bfloat16 h = __float2bfloat16_rn(w);
        __nv_bfloat16 m = __float2bfloat16_rn(w - __bfloat162float(h));
        *(unsigned short*)(smem + SM_W3H + n * WSTR23 + k * 2) = __bfloat16_as_ushort(h);
        *(unsigned short*)(smem + SM_W3M + n * WSTR23 + k * 2) = __bfloat16_as_ushort(m);
    }
    __syncthreads();

    char* actHp = smem + SM_ACT + wid * ACTW;
    char* actMp = actHp + 5632;
    const uint32_t actH_u = sb + SM_ACT + wid * ACTW;
    const uint32_t actM_u = actH_u + 5632;
    const uint32_t aH = actH_u + (lane & 15) * ASTRIDE + (lane >> 4) * 16;
    const uint32_t aM = actM_u + (lane & 15) * ASTRIDE + (lane >> 4) * 16;
    // x4-style lane offsets for B (16-row window)
    const uint32_t wlx1 = (lane & 15) * WSTR1  + (lane >> 4) * 16;
    const uint32_t wlx2 = (lane & 15) * WSTR23 + (lane >> 4) * 16;
    const uint32_t w1H = sb + SM_W1H + wlx1, w1M = sb + SM_W1M + wlx1;
    const uint32_t w2H = sb + SM_W2H + wlx2, w2M = sb + SM_W2M + wlx2;
    const uint32_t w3H = sb + SM_W3H + wlx2, w3M = sb + SM_W3M + wlx2;

#pragma unroll 1
    for (int cc = 0; cc < 4; cc++) {
        const int centroid = blockIdx.x * 32 + wid * 4 + cc;
        const int b = centroid >> 10;
        const int nid = d_ball[(size_t)centroid * KNBR + lane];

        __syncwarp();
        {
            float arr[80];
            const float4* pr = (const float4*)(pts + ((size_t)b * NPTS + nid) * CIN);
#pragma unroll
            for (int q = 0; q < 16; q++) {
                float4 v = pr[q];
                arr[4 * q] = v.x; arr[4 * q + 1] = v.y; arr[4 * q + 2] = v.z; arr[4 * q + 3] = v.w;
            }
            const float* xr = xyz + ((size_t)b * NPTS + nid) * 3;
            const float* nc = new_xyz + (size_t)centroid * 3;
            arr[64] = __fsub_rn(xr[0], nc[0]);
            arr[65] = __fsub_rn(xr[1], nc[1]);
            arr[66] = __fsub_rn(xr[2], nc[2]);
#pragma unroll
            for (int i = 67; i < 80; i++) arr[i] = 0.f;

            uint32_t* rowH = (uint32_t*)(actHp + lane * ASTRIDE);
            uint32_t* rowM = (uint32_t*)(actMp + lane * ASTRIDE);
#pragma unroll
            for (int i = 0; i < 40; i++) {
                rowH[i] = pk_hi(arr[2 * i], arr[2 * i + 1]);
                rowM[i] = pk_mid(arr[2 * i], arr[2 * i + 1]);
            }
        }
        __syncwarp();

        float acc[2][8][4];
        run_layer<5, WSTR1>(aH, aM, w1H, w1M, acc);
        __syncwarp();
        epi_store(acc, actHp, actMp, b0s, lane);
        __syncwarp();
        run_layer<4, WSTR23>(aH, aM, w2H, w2M, acc);
        __syncwarp();
        epi_store(acc, actHp, actMp, b1s, lane);
        __syncwarp();
        float* outp = new_points + (size_t)centroid * 128;
        run_layer<4, WSTR23>(aH, aM, w3H, w3M, acc);
        epi_max(acc, b2s, outp, 0, lane);
        run_layer<4, WSTR23>(aH, aM, w3H + 64 * WSTR23, w3M + 64 * WSTR23, acc);
        epi_max(acc, b2s, outp, 64, lane);
    }
}

// ---------------------------------------------------------------------------
extern "C" void kernel_launch(void* const* d_in, const int* in_sizes, int n_in,
                              void* d_out, int out_size)
{
    (void)in_sizes; (void)n_in; (void)out_size;
    const float* xyz = (const float*)d_in[0];
    const float* pts = (const float*)d_in[1];
    const float* w0  = (const float*)d_in[2];
    const float* b0  = (const float*)d_in[3];
    const float* w1  = (const float*)d_in[4];
    const float* b1  = (const float*)d_in[5];
    const float* w2  = (const float*)d_in[6];
    const float* b2  = (const float*)d_in[7];

    float* out      = (float*)d_out;
    float* new_xyz  = out;
    float* new_pts  = out + (size_t)BATCH * NSAMP * 3;

    const int FPS_SMEM = NPTS * 16 + 64;        // float4 xyz + atomic slots
    const int MLP_SMEM = SM_MLP_END;

    cudaFuncSetAttribute(fps_kernel, cudaFuncAttributeMaxDynamicSharedMemorySize, FPS_SMEM);
    cudaFuncSetAttribute(mlp_kernel, cudaFuncAttributeMaxDynamicSharedMemorySize, MLP_SMEM);

    fps_kernel<<<BATCH, 256, FPS_SMEM>>>(xyz, new_xyz);
    query_kernel<<<(BATCH * NSAMP) / 8, 256>>>(xyz, new_xyz);
    mlp_kernel<<<(BATCH * NSAMP) / 32, 256, MLP_SMEM>>>(
        xyz, pts, w0, b0, w1, b1, w2, b2, new_xyz, new_pts);
}

// round 7
// speedup vs baseline: 1.2498x; 1.2498x over previous
#include <cuda_runtime.h>
#include <cuda_bf16.h>
#include <cstdint>

#define BATCH 16
#define NPTS  4096
#define CIN   64
#define NSAMP 1024
#define KNBR  32
#define FULLM 0xffffffffu

// ---------------- f32x2 helpers (FPS only) ----------------
#define PACKF2(d, lo, hi)  asm("mov.b64 %0, {%1, %2};" : "=l"(d) : "f"(lo), "f"(hi))
#define UNPACKF2(lo, hi, s) asm("mov.b64 {%0, %1}, %2;" : "=f"(lo), "=f"(hi) : "l"(s))
#define ADD2(d, a, b) asm("add.rn.f32x2 %0, %1, %2;" : "=l"(d) : "l"(a), "l"(b))
#define MUL2(d, a, b) asm("mul.rn.f32x2 %0, %1, %2;" : "=l"(d) : "l"(a), "l"(b))

__device__ int d_ball[BATCH * NSAMP * KNBR];

#define AMAX(vA, jA, vB, jB, vO, jO) { bool g_ = ((vB) > (vA)); (vO) = g_ ? (vB) : (vA); (jO) = g_ ? (jB) : (jA); }

// ---------------------------------------------------------------------------
// Kernel 1: FPS. float4 xyz in shared, R3-style warp REDUX argmax, then
// cross-warp combine via serial u64 key max in registers (no 2nd REDUX).
// ---------------------------------------------------------------------------
__global__ __launch_bounds__(256) void fps_kernel(const float* __restrict__ xyz,
                                                  float* __restrict__ new_xyz)
{
    extern __shared__ float sm[];
    float4* sxyz = (float4*)sm;                                        // 4096*16B
    unsigned long long* sred = (unsigned long long*)(sm + NPTS * 4);   // [2][8]

    const int b = blockIdx.x, tid = threadIdx.x;
    const int lane = tid & 31, warp = tid >> 5;
    const float* gx = xyz + (size_t)b * NPTS * 3;

    for (int i = tid; i < NPTS; i += 256) {
        float4 v;
        v.x = gx[3 * i]; v.y = gx[3 * i + 1]; v.z = gx[3 * i + 2]; v.w = 0.f;
        sxyz[i] = v;
    }
    __syncthreads();

    // register-resident points: slot j -> global index tid + j*256
    unsigned long long px[8], py[8], pz[8];
    float dist[16];
#pragma unroll
    for (int q = 0; q < 8; q++) {
        float4 a = sxyz[tid + (2 * q) * 256];
        float4 c = sxyz[tid + (2 * q + 1) * 256];
        PACKF2(px[q], a.x, c.x);
        PACKF2(py[q], a.y, c.y);
        PACKF2(pz[q], a.z, c.z);
        dist[2 * q] = 1e10f; dist[2 * q + 1] = 1e10f;
    }

    int far = 0;
    for (int t = 0; t < NSAMP; t++) {
        float4 cen = sxyz[far];
        if (tid == 0) {
            float* o = new_xyz + ((size_t)b * NSAMP + t) * 3;
            o[0] = cen.x; o[1] = cen.y; o[2] = cen.z;
        }
        unsigned long long ncx, ncy, ncz;
        float mx = -cen.x, my = -cen.y, mz = -cen.z;
        PACKF2(ncx, mx, mx); PACKF2(ncy, my, my); PACKF2(ncz, mz, mz);

        float v[16];
#pragma unroll
        for (int q = 0; q < 8; q++) {
            unsigned long long dx, dy, dz, xx, yy, zz, s, d2;
            ADD2(dx, px[q], ncx);                 // p + (-c) == p - c exactly
            ADD2(dy, py[q], ncy);
            ADD2(dz, pz[q], ncz);
            MUL2(xx, dx, dx); MUL2(yy, dy, dy); MUL2(zz, dz, dz);
            ADD2(s, xx, yy); ADD2(d2, s, zz);     // (x²+y²)+z² order
            float d0, d1;
            UNPACKF2(d0, d1, d2);
            float n0 = fminf(dist[2 * q], d0);     dist[2 * q] = n0;     v[2 * q] = n0;
            float n1 = fminf(dist[2 * q + 1], d1); dist[2 * q + 1] = n1; v[2 * q + 1] = n1;
        }
        // tree argmax over 16 slots (min slot on ties -> min index)
        float va[8]; int ja[8];
#pragma unroll
        for (int q = 0; q < 8; q++) AMAX(v[2 * q], 2 * q, v[2 * q + 1], 2 * q + 1, va[q], ja[q]);
        float vb[4]; int jb[4];
#pragma unroll
        for (int q = 0; q < 4; q++) AMAX(va[2 * q], ja[2 * q], va[2 * q + 1], ja[2 * q + 1], vb[q], jb[q]);
        float vc0, vc1; int jc0, jc1;
        AMAX(vb[0], jb[0], vb[1], jb[1], vc0, jc0);
        AMAX(vb[2], jb[2], vb[3], jb[3], vc1, jc1);
        float mv; int mj;
        AMAX(vc0, jc0, vc1, jc1, mv, mj);
        int bi = tid + mj * 256;

        // warp argmax: max bits; among equals max(4095-idx) = min idx
        unsigned bits = __float_as_uint(mv);
        unsigned wmax = __reduce_max_sync(FULLM, bits);
        unsigned cand = (bits == wmax) ? (unsigned)(4095 - bi) : 0u;
        unsigned winv = __reduce_max_sync(FULLM, cand);

        const int pt = t & 1;
        if (lane == 0)
            sred[pt * 8 + warp] = ((unsigned long long)wmax << 32) | winv;
        __syncthreads();
        // cross-warp combine: 8 keys, serial register max (every thread, uniform)
        const ulonglong2* kr = (const ulonglong2*)(sred + pt * 8);
        ulonglong2 k0 = kr[0], k1 = kr[1], k2 = kr[2], k3 = kr[3];
        unsigned long long m0 = k0.x > k0.y ? k0.x : k0.y;
        unsigned long long m1 = k1.x > k1.y ? k1.x : k1.y;
        unsigned long long m2 = k2.x > k2.y ? k2.x : k2.y;
        unsigned long long m3 = k3.x > k3.y ? k3.x : k3.y;
        unsigned long long ma = m0 > m1 ? m0 : m1;
        unsigned long long mb = m2 > m3 ? m2 : m3;
        unsigned long long mm = ma > mb ? ma : mb;
        far = 4095 - (int)(unsigned)(mm & 0xffffffffull);
    }
}

// ---------------------------------------------------------------------------
// Kernel 2: ball query (unchanged)
// ---------------------------------------------------------------------------
__global__ __launch_bounds__(256) void query_kernel(const float* __restrict__ xyz,
                                                    const float* __restrict__ new_xyz)
{
    const int warp = threadIdx.x >> 5, lane = threadIdx.x & 31;
    const int gs = blockIdx.x * 8 + warp;
    const int b  = gs >> 10;
    const float* nc = new_xyz + (size_t)gs * 3;
    const float cx = nc[0], cy = nc[1], cz = nc[2];
    const float* gx = xyz + (size_t)b * NPTS * 3;
    int* out = d_ball + (size_t)gs * KNBR;
    const float R2 = 0.04f;

    int cnt = 0, first = -1;
    for (int base = 0; base < NPTS && cnt < KNBR; base += 32) {
        int j = base + lane;
        float dx = __fsub_rn(cx, gx[3 * j]);
        float dy = __fsub_rn(cy, gx[3 * j + 1]);
        float dz = __fsub_rn(cz, gx[3 * j + 2]);
        float d2 = __fadd_rn(__fadd_rn(__fmul_rn(dx, dx), __fmul_rn(dy, dy)),
                             __fmul_rn(dz, dz));
        bool in = (d2 <= R2);
        unsigned m = __ballot_sync(FULLM, in);
        int pos = cnt + __popc(m & ((1u << lane) - 1u));
        if (in && pos < KNBR) {
            out[pos] = j;
            if (pos == 0) first = j;
        }
        cnt += __popc(m);
    }
    unsigned hf = __ballot_sync(FULLM, first >= 0);
    int src = __ffs(hf) - 1;
    first = __shfl_sync(FULLM, first, src);
    int filled = cnt < KNBR ? cnt : KNBR;
    if (lane >= filled) out[lane] = first;
}

// ---------------------------------------------------------------------------
// Kernel 3: MLP via mma.sync (m16n8k16 bf16, 3-term hi/mid split).
// R5 structure (ldsm2 for B), packed bf16x2 conversions in gather/epilogue.
// ---------------------------------------------------------------------------
#define ASTRIDE  176
#define WSTR1    176
#define WSTR23   144
#define SM_BIAS  0
#define SM_W1H   1024
#define SM_W1M   12288
#define SM_W2H   23552
#define SM_W2M   32768
#define SM_W3H   41984
#define SM_W3M   60416
#define SM_ACT   78848
#define ACTW     11264
#define SM_MLP_END (78848 + 8 * ACTW)   // 168960

// packed bf16x2 convert: lo -> low half, hi -> high half (rn, same as scalar)
__device__ __forceinline__ unsigned cvt2(float lo, float hi) {
    unsigned r;
    asm("cvt.rn.bf16x2.f32 %0, %1, %2;" : "=r"(r) : "f"(hi), "f"(lo));
    return r;
}
// residual pair given the already-computed hi pair (exact bf16->f32 via bit ops)
__device__ __forceinline__ unsigned mid2(float lo, float hi, unsigned h2) {
    float lh = __uint_as_float(h2 << 16);
    float hh = __uint_as_float(h2 & 0xffff0000u);
    return cvt2(lo - lh, hi - hh);
}
__device__ __forceinline__ uint32_t smem_u32(const void* p) {
    uint32_t a;
    asm("{ .reg .u64 t; cvta.to.shared.u64 t, %1; cvt.u32.u64 %0, t; }" : "=r"(a) : "l"(p));
    return a;
}
__device__ __forceinline__ void ldsm4(uint32_t* r, uint32_t addr) {
    asm volatile("ldmatrix.sync.aligned.m8n8.x4.shared.b16 {%0,%1,%2,%3}, [%4];"
        : "=r"(r[0]), "=r"(r[1]), "=r"(r[2]), "=r"(r[3]) : "r"(addr));
}
__device__ __forceinline__ void ldsm2(uint32_t* r, uint32_t addr) {
    asm volatile("ldmatrix.sync.aligned.m8n8.x2.shared.b16 {%0,%1}, [%2];"
        : "=r"(r[0]), "=r"(r[1]) : "r"(addr));
}
__device__ __forceinline__ void mma_bf16(float* d, const uint32_t* a, const uint32_t* b) {
    asm volatile("mma.sync.aligned.m16n8k16.row.col.f32.bf16.bf16.f32 "
        "{%0,%1,%2,%3}, {%4,%5,%6,%7}, {%8,%9}, {%0,%1,%2,%3};"
        : "+f"(d[0]), "+f"(d[1]), "+f"(d[2]), "+f"(d[3])
        : "r"(a[0]), "r"(a[1]), "r"(a[2]), "r"(a[3]), "r"(b[0]), "r"(b[1]));
}

template<int KT, int WSTR>
__device__ __forceinline__ void run_layer(uint32_t aH, uint32_t aM,
                                          uint32_t wHb, uint32_t wMb,
                                          float acc[2][8][4])
{
#pragma unroll
    for (int m = 0; m < 2; m++)
#pragma unroll
        for (int n = 0; n < 8; n++)
#pragma unroll
            for (int q = 0; q < 4; q++) acc[m][n][q] = 0.f;
#pragma unroll
    for (int k = 0; k < KT; k++) {
        uint32_t ah[2][4], am[2][4];
        ldsm4(ah[0], aH + k * 32);
        ldsm4(ah[1], aH + 16 * ASTRIDE + k * 32);
        ldsm4(am[0], aM + k * 32);
        ldsm4(am[1], aM + 16 * ASTRIDE + k * 32);
#pragma unroll
        for (int n = 0; n < 8; n++) {
            uint32_t bh[2], bm[2];
            ldsm2(bh, wHb + n * 8 * WSTR + k * 32);
            ldsm2(bm, wMb + n * 8 * WSTR + k * 32);
#pragma unroll
            for (int m = 0; m < 2; m++) {
                mma_bf16(acc[m][n], ah[m], bh);
                mma_bf16(acc[m][n], am[m], bh);
                mma_bf16(acc[m][n], ah[m], bm);
            }
        }
    }
}

__device__ __forceinline__ void epi_store(float acc[2][8][4],
    char* actH, char* actM, const float* bias, int lane)
{
    const int cg = lane & 3, rg = lane >> 2;
#pragma unroll
    for (int m = 0; m < 2; m++) {
#pragma unroll
        for (int n = 0; n < 8; n++) {
            int n0 = n * 8 + 2 * cg;
            float b0v = bias[n0], b1v = bias[n0 + 1];
            float x0 = fmaxf(acc[m][n][0] + b0v, 0.f);
            float x1 = fmaxf(acc[m][n][1] + b1v, 0.f);
            float x2 = fmaxf(acc[m][n][2] + b0v, 0.f);
            float x3 = fmaxf(acc[m][n][3] + b1v, 0.f);
            int r0 = m * 16 + rg, r1 = r0 + 8;
            unsigned h01 = cvt2(x0, x1), h23 = cvt2(x2, x3);
            *(uint32_t*)(actH + r0 * ASTRIDE + n0 * 2) = h01;
            *(uint32_t*)(actH + r1 * ASTRIDE + n0 * 2) = h23;
            *(uint32_t*)(actM + r0 * ASTRIDE + n0 * 2) = mid2(x0, x1, h01);
            *(uint32_t*)(actM + r1 * ASTRIDE + n0 * 2) = mid2(x2, x3, h23);
        }
    }
}

__device__ __forceinline__ void epi_max(float acc[2][8][4], const float* bias,
                                        float* outp, int nbase, int lane)
{
    const int cg = lane & 3;
#pragma unroll
    for (int n = 0; n < 8; n++) {
        int n0 = nbase + n * 8 + 2 * cg;
        float b0v = bias[n0], b1v = bias[n0 + 1];
        float v0 = fmaxf(fmaxf(acc[0][n][0] + b0v, 0.f), fmaxf(acc[0][n][2] + b0v, 0.f));
        v0 = fmaxf(v0, fmaxf(fmaxf(acc[1][n][0] + b0v, 0.f), fmaxf(acc[1][n][2] + b0v, 0.f)));
        float v1 = fmaxf(fmaxf(acc[0][n][1] + b1v, 0.f), fmaxf(acc[0][n][3] + b1v, 0.f));
        v1 = fmaxf(v1, fmaxf(fmaxf(acc[1][n][1] + b1v, 0.f), fmaxf(acc[1][n][3] + b1v, 0.f)));
#pragma unroll
        for (int o = 4; o <= 16; o <<= 1) {
            v0 = fmaxf(v0, __shfl_xor_sync(FULLM, v0, o));
            v1 = fmaxf(v1, __shfl_xor_sync(FULLM, v1, o));
        }
        if (lane < 4) { outp[n0] = v0; outp[n0 + 1] = v1; }
    }
}

__global__ __launch_bounds__(256) void mlp_kernel(
    const float* __restrict__ xyz, const float* __restrict__ pts,
    const float* __restrict__ w0, const float* __restrict__ b0,
    const float* __restrict__ w1, const float* __restrict__ b1,
    const float* __restrict__ w2, const float* __restrict__ b2,
    const float* __restrict__ new_xyz, float* __restrict__ new_points)
{
    extern __shared__ char smem[];
    const uint32_t sb = smem_u32(smem);
    const int tid = threadIdx.x, wid = tid >> 5, lane = tid & 31;

    float* b0s = (float*)(smem + SM_BIAS);
    float* b1s = b0s + 64;
    float* b2s = b1s + 64;
    if (tid < 64) { b0s[tid] = b0[tid]; b1s[tid] = b1[tid]; }
    if (tid < 128) b2s[tid] = b2[tid];

    for (int idx = tid; idx < 64 * 80; idx += 256) {
        int n = idx / 80, k = idx - n * 80;
        float w = (k < 67) ? w0[k * 64 + n] : 0.f;
        __nv_bfloat16 h = __float2bfloat16_rn(w);
        __nv_bfloat16 m = __float2bfloat16_rn(w - __bfloat162float(h));
        *(unsigned short*)(smem + SM_W1H + n * WSTR1 + k * 2) = __bfloat16_as_ushort(h);
        *(unsigned short*)(smem + SM_W1M + n * WSTR1 + k * 2) = __bfloat16_as_ushort(m);
    }
    for (int idx = tid; idx < 64 * 64; idx += 256) {
        int n = idx >> 6, k = idx & 63;
        float w = w1[k * 64 + n];
        __nv_bfloat16 h = __float2bfloat16_rn(w);
        __nv_bfloat16 m = __float2bfloat16_rn(w - __bfloat162float(h));
        *(unsigned short*)(smem + SM_W2H + n * WSTR23 + k * 2) = __bfloat16_as_ushort(h);
        *(unsigned short*)(smem + SM_W2M + n * WSTR23 + k * 2) = __bfloat16_as_ushort(m);
    }
    for (int idx = tid; idx < 128 * 64; idx += 256) {
        int n = idx >> 6, k = idx & 63;
        float w = w2[k * 128 + n];
        __nv_bfloat16 h = __float2bfloat16_rn(w);
        __nv_bfloat16 m = __float2bfloat16_rn(w - __bfloat162float(h));
        *(unsigned short*)(smem + SM_W3H + n * WSTR23 + k * 2) = __bfloat16_as_ushort(h);
        *(unsigned short*)(smem + SM_W3M + n * WSTR23 + k * 2) = __bfloat16_as_ushort(m);
    }
    __syncthreads();

    char* actHp = smem + SM_ACT + wid * ACTW;
    char* actMp = actHp + 5632;
    const uint32_t actH_u = sb + SM_ACT + wid * ACTW;
    const uint32_t actM_u = actH_u + 5632;
    const uint32_t aH = actH_u + (lane & 15) * ASTRIDE + (lane >> 4) * 16;
    const uint32_t aM = actM_u + (lane & 15) * ASTRIDE + (lane >> 4) * 16;
    const int bl = lane & 15;
    const uint32_t wl1 = (bl & 7) * WSTR1  + ((bl >> 3) & 1) * 16;
    const uint32_t wl2 = (bl & 7) * WSTR23 + ((bl >> 3) & 1) * 16;
    const uint32_t w1H = sb + SM_W1H + wl1, w1M = sb + SM_W1M + wl1;
    const uint32_t w2H = sb + SM_W2H + wl2, w2M = sb + SM_W2M + wl2;
    const uint32_t w3H = sb + SM_W3H + wl2, w3M = sb + SM_W3M + wl2;

#pragma unroll 1
    for (int cc = 0; cc < 4; cc++) {
        const int centroid = blockIdx.x * 32 + wid * 4 + cc;
        const int b = centroid >> 10;
        const int nid = d_ball[(size_t)centroid * KNBR + lane];

        __syncwarp();
        {
            float arr[80];
            const float4* pr = (const float4*)(pts + ((size_t)b * NPTS + nid) * CIN);
#pragma unroll
            for (int q = 0; q < 16; q++) {
                float4 v = pr[q];
                arr[4 * q] = v.x; arr[4 * q + 1] = v.y; arr[4 * q + 2] = v.z; arr[4 * q + 3] = v.w;
            }
            const float* xr = xyz + ((size_t)b * NPTS + nid) * 3;
            const float* nc = new_xyz + (size_t)centroid * 3;
            arr[64] = __fsub_rn(xr[0], nc[0]);
            arr[65] = __fsub_rn(xr[1], nc[1]);
            arr[66] = __fsub_rn(xr[2], nc[2]);
#pragma unroll
            for (int i = 67; i < 80; i++) arr[i] = 0.f;

            uint32_t* rowH = (uint32_t*)(actHp + lane * ASTRIDE);
            uint32_t* rowM = (uint32_t*)(actMp + lane * ASTRIDE);
#pragma unroll
            for (int i = 0; i < 40; i++) {
                unsigned h = cvt2(arr[2 * i], arr[2 * i + 1]);
                rowH[i] = h;
                rowM[i] = mid2(arr[2 * i], arr[2 * i + 1], h);
            }
        }
        __syncwarp();

        float acc[2][8][4];
        run_layer<5, WSTR1>(aH, aM, w1H, w1M, acc);
        __syncwarp();
        epi_store(acc, actHp, actMp, b0s, lane);
        __syncwarp();
        run_layer<4, WSTR23>(aH, aM, w2H, w2M, acc);
        __syncwarp();
        epi_store(acc, actHp, actMp, b1s, lane);
        __syncwarp();
        float* outp = new_points + (size_t)centroid * 128;
        run_layer<4, WSTR23>(aH, aM, w3H, w3M, acc);
        epi_max(acc, b2s, outp, 0, lane);
        run_layer<4, WSTR23>(aH, aM, w3H + 64 * WSTR23, w3M + 64 * WSTR23, acc);
        epi_max(acc, b2s, outp, 64, lane);
    }
}

// ---------------------------------------------------------------------------
extern "C" void kernel_launch(void* const* d_in, const int* in_sizes, int n_in,
                              void* d_out, int out_size)
{
    (void)in_sizes; (void)n_in; (void)out_size;
    const float* xyz = (const float*)d_in[0];
    const float* pts = (const float*)d_in[1];
    const float* w0  = (const float*)d_in[2];
    const float* b0  = (const float*)d_in[3];
    const float* w1  = (const float*)d_in[4];
    const float* b1  = (const float*)d_in[5];
    const float* w2  = (const float*)d_in[6];
    const float* b2  = (const float*)d_in[7];

    float* out      = (float*)d_out;
    float* new_xyz  = out;
    float* new_pts  = out + (size_t)BATCH * NSAMP * 3;

    const int FPS_SMEM = NPTS * 16 + 128;       // float4 xyz + key slots
    const int MLP_SMEM = SM_MLP_END;

    cudaFuncSetAttribute(fps_kernel, cudaFuncAttributeMaxDynamicSharedMemorySize, FPS_SMEM);
    cudaFuncSetAttribute(mlp_kernel, cudaFuncAttributeMaxDynamicSharedMemorySize, MLP_SMEM);

    fps_kernel<<<BATCH, 256, FPS_SMEM>>>(xyz, new_xyz);
    query_kernel<<<(BATCH * NSAMP) / 8, 256>>>(xyz, new_xyz);
    mlp_kernel<<<(BATCH * NSAMP) / 32, 256, MLP_SMEM>>>(
        xyz, pts, w0, b0, w1, b1, w2, b2, new_xyz, new_pts);
}

// round 9
// speedup vs baseline: 1.2678x; 1.0144x over previous
#include <cuda_runtime.h>
#include <cuda_bf16.h>
#include <cstdint>

#define BATCH 16
#define NPTS  4096
#define CIN   64
#define NSAMP 1024
#define KNBR  32
#define FULLM 0xffffffffu

// ---------------- f32x2 helpers (FPS only) ----------------
#define PACKF2(d, lo, hi)  asm("mov.b64 %0, {%1, %2};" : "=l"(d) : "f"(lo), "f"(hi))
#define UNPACKF2(lo, hi, s) asm("mov.b64 {%0, %1}, %2;" : "=f"(lo), "=f"(hi) : "l"(s))
#define ADD2(d, a, b) asm("add.rn.f32x2 %0, %1, %2;" : "=l"(d) : "l"(a), "l"(b))
#define MUL2(d, a, b) asm("mul.rn.f32x2 %0, %1, %2;" : "=l"(d) : "l"(a), "l"(b))

__device__ int d_ball[BATCH * NSAMP * KNBR];

#define AMAX(vA, jA, vB, jB, vO, jO) { bool g_ = ((vB) > (vA)); (vO) = g_ ? (vB) : (vA); (jO) = g_ ? (jB) : (jA); }

// ---------------------------------------------------------------------------
// Kernel 1: FPS (unchanged from R7 — 342us, bit-exact)
// ---------------------------------------------------------------------------
__global__ __launch_bounds__(256) void fps_kernel(const float* __restrict__ xyz,
                                                  float* __restrict__ new_xyz)
{
    extern __shared__ float sm[];
    float4* sxyz = (float4*)sm;
    unsigned long long* sred = (unsigned long long*)(sm + NPTS * 4);

    const int b = blockIdx.x, tid = threadIdx.x;
    const int lane = tid & 31, warp = tid >> 5;
    const float* gx = xyz + (size_t)b * NPTS * 3;

    for (int i = tid; i < NPTS; i += 256) {
        float4 v;
        v.x = gx[3 * i]; v.y = gx[3 * i + 1]; v.z = gx[3 * i + 2]; v.w = 0.f;
        sxyz[i] = v;
    }
    __syncthreads();

    unsigned long long px[8], py[8], pz[8];
    float dist[16];
#pragma unroll
    for (int q = 0; q < 8; q++) {
        float4 a = sxyz[tid + (2 * q) * 256];
        float4 c = sxyz[tid + (2 * q + 1) * 256];
        PACKF2(px[q], a.x, c.x);
        PACKF2(py[q], a.y, c.y);
        PACKF2(pz[q], a.z, c.z);
        dist[2 * q] = 1e10f; dist[2 * q + 1] = 1e10f;
    }

    int far = 0;
    for (int t = 0; t < NSAMP; t++) {
        float4 cen = sxyz[far];
        if (tid == 0) {
            float* o = new_xyz + ((size_t)b * NSAMP + t) * 3;
            o[0] = cen.x; o[1] = cen.y; o[2] = cen.z;
        }
        unsigned long long ncx, ncy, ncz;
        float mx = -cen.x, my = -cen.y, mz = -cen.z;
        PACKF2(ncx, mx, mx); PACKF2(ncy, my, my); PACKF2(ncz, mz, mz);

        float v[16];
#pragma unroll
        for (int q = 0; q < 8; q++) {
            unsigned long long dx, dy, dz, xx, yy, zz, s, d2;
            ADD2(dx, px[q], ncx);
            ADD2(dy, py[q], ncy);
            ADD2(dz, pz[q], ncz);
            MUL2(xx, dx, dx); MUL2(yy, dy, dy); MUL2(zz, dz, dz);
            ADD2(s, xx, yy); ADD2(d2, s, zz);
            float d0, d1;
            UNPACKF2(d0, d1, d2);
            float n0 = fminf(dist[2 * q], d0);     dist[2 * q] = n0;     v[2 * q] = n0;
            float n1 = fminf(dist[2 * q + 1], d1); dist[2 * q + 1] = n1; v[2 * q + 1] = n1;
        }
        float va[8]; int ja[8];
#pragma unroll
        for (int q = 0; q < 8; q++) AMAX(v[2 * q], 2 * q, v[2 * q + 1], 2 * q + 1, va[q], ja[q]);
        float vb[4]; int jb[4];
#pragma unroll
        for (int q = 0; q < 4; q++) AMAX(va[2 * q], ja[2 * q], va[2 * q + 1], ja[2 * q + 1], vb[q], jb[q]);
        float vc0, vc1; int jc0, jc1;
        AMAX(vb[0], jb[0], vb[1], jb[1], vc0, jc0);
        AMAX(vb[2], jb[2], vb[3], jb[3], vc1, jc1);
        float mv; int mj;
        AMAX(vc0, jc0, vc1, jc1, mv, mj);
        int bi = tid + mj * 256;

        unsigned bits = __float_as_uint(mv);
        unsigned wmax = __reduce_max_sync(FULLM, bits);
        unsigned cand = (bits == wmax) ? (unsigned)(4095 - bi) : 0u;
        unsigned winv = __reduce_max_sync(FULLM, cand);

        const int pt = t & 1;
        if (lane == 0)
            sred[pt * 8 + warp] = ((unsigned long long)wmax << 32) | winv;
        __syncthreads();
        const ulonglong2* kr = (const ulonglong2*)(sred + pt * 8);
        ulonglong2 k0 = kr[0], k1 = kr[1], k2 = kr[2], k3 = kr[3];
        unsigned long long m0 = k0.x > k0.y ? k0.x : k0.y;
        unsigned long long m1 = k1.x > k1.y ? k1.x : k1.y;
        unsigned long long m2 = k2.x > k2.y ? k2.x : k2.y;
        unsigned long long m3 = k3.x > k3.y ? k3.x : k3.y;
        unsigned long long ma = m0 > m1 ? m0 : m1;
        unsigned long long mb = m2 > m3 ? m2 : m3;
        unsigned long long mm = ma > mb ? ma : mb;
        far = 4095 - (int)(unsigned)(mm & 0xffffffffull);
    }
}

// ---------------------------------------------------------------------------
// Kernel 2: ball query (unchanged)
// ---------------------------------------------------------------------------
__global__ __launch_bounds__(256) void query_kernel(const float* __restrict__ xyz,
                                                    const float* __restrict__ new_xyz)
{
    const int warp = threadIdx.x >> 5, lane = threadIdx.x & 31;
    const int gs = blockIdx.x * 8 + warp;
    const int b  = gs >> 10;
    const float* nc = new_xyz + (size_t)gs * 3;
    const float cx = nc[0], cy = nc[1], cz = nc[2];
    const float* gx = xyz + (size_t)b * NPTS * 3;
    int* out = d_ball + (size_t)gs * KNBR;
    const float R2 = 0.04f;

    int cnt = 0, first = -1;
    for (int base = 0; base < NPTS && cnt < KNBR; base += 32) {
        int j = base + lane;
        float dx = __fsub_rn(cx, gx[3 * j]);
        float dy = __fsub_rn(cy, gx[3 * j + 1]);
        float dz = __fsub_rn(cz, gx[3 * j + 2]);
        float d2 = __fadd_rn(__fadd_rn(__fmul_rn(dx, dx), __fmul_rn(dy, dy)),
                             __fmul_rn(dz, dz));
        bool in = (d2 <= R2);
        unsigned m = __ballot_sync(FULLM, in);
        int pos = cnt + __popc(m & ((1u << lane) - 1u));
        if (in && pos < KNBR) {
            out[pos] = j;
            if (pos == 0) first = j;
        }
        cnt += __popc(m);
    }
    unsigned hf = __ballot_sync(FULLM, first >= 0);
    int src = __ffs(hf) - 1;
    first = __shfl_sync(FULLM, first, src);
    int filled = cnt < KNBR ? cnt : KNBR;
    if (lane >= filled) out[lane] = first;
}

// ---------------------------------------------------------------------------
// Kernel 3: MLP via mma.sync, register-resident inter-layer fragments.
// Layer 1: A from smem via ldmatrix. Layers 2/3: A fragments built directly
// from accumulators (acc n-cols == next A k-cols, same lane) — no smem
// round-trip, no A-ldsm, no syncwarp.
// ---------------------------------------------------------------------------
#define ASTRIDE  176
#define WSTR1    176
#define WSTR23   144
#define SM_BIAS  0
#define SM_W1H   1024
#define SM_W1M   12288
#define SM_W2H   23552
#define SM_W2M   32768
#define SM_W3H   41984
#define SM_W3M   60416
#define SM_ACT   78848
#define ACTW     11264
#define SM_MLP_END (78848 + 8 * ACTW)   // 168960

__device__ __forceinline__ unsigned cvt2(float lo, float hi) {
    unsigned r;
    asm("cvt.rn.bf16x2.f32 %0, %1, %2;" : "=r"(r) : "f"(hi), "f"(lo));
    return r;
}
__device__ __forceinline__ unsigned mid2(float lo, float hi, unsigned h2) {
    float lh = __uint_as_float(h2 << 16);
    float hh = __uint_as_float(h2 & 0xffff0000u);
    return cvt2(lo - lh, hi - hh);
}
__device__ __forceinline__ uint32_t smem_u32(const void* p) {
    uint32_t a;
    asm("{ .reg .u64 t; cvta.to.shared.u64 t, %1; cvt.u32.u64 %0, t; }" : "=r"(a) : "l"(p));
    return a;
}
__device__ __forceinline__ void ldsm4(uint32_t* r, uint32_t addr) {
    asm volatile("ldmatrix.sync.aligned.m8n8.x4.shared.b16 {%0,%1,%2,%3}, [%4];"
        : "=r"(r[0]), "=r"(r[1]), "=r"(r[2]), "=r"(r[3]) : "r"(addr));
}
__device__ __forceinline__ void ldsm2(uint32_t* r, uint32_t addr) {
    asm volatile("ldmatrix.sync.aligned.m8n8.x2.shared.b16 {%0,%1}, [%2];"
        : "=r"(r[0]), "=r"(r[1]) : "r"(addr));
}
__device__ __forceinline__ void mma_bf16(float* d, const uint32_t* a, const uint32_t* b) {
    asm volatile("mma.sync.aligned.m16n8k16.row.col.f32.bf16.bf16.f32 "
        "{%0,%1,%2,%3}, {%4,%5,%6,%7}, {%8,%9}, {%0,%1,%2,%3};"
        : "+f"(d[0]), "+f"(d[1]), "+f"(d[2]), "+f"(d[3])
        : "r"(a[0]), "r"(a[1]), "r"(a[2]), "r"(a[3]), "r"(b[0]), "r"(b[1]));
}

// Layer 1: A hi/mid from smem via ldmatrix, B hi/mid via ldsm2.
__device__ __forceinline__ void run_layer1(uint32_t aH, uint32_t aM,
                                           uint32_t wHb, uint32_t wMb,
                                           float acc[2][8][4])
{
#pragma unroll
    for (int m = 0; m < 2; m++)
#pragma unroll
        for (int n = 0; n < 8; n++)
#pragma unroll
            for (int q = 0; q < 4; q++) acc[m][n][q] = 0.f;
#pragma unroll
    for (int k = 0; k < 5; k++) {
        uint32_t ah[2][4], am[2][4];
        ldsm4(ah[0], aH + k * 32);
        ldsm4(ah[1], aH + 16 * ASTRIDE + k * 32);
        ldsm4(am[0], aM + k * 32);
        ldsm4(am[1], aM + 16 * ASTRIDE + k * 32);
#pragma unroll
        for (int n = 0; n < 8; n++) {
            uint32_t bh[2], bm[2];
            ldsm2(bh, wHb + n * 8 * WSTR1 + k * 32);
            ldsm2(bm, wMb + n * 8 * WSTR1 + k * 32);
#pragma unroll
            for (int m = 0; m < 2; m++) {
                mma_bf16(acc[m][n], ah[m], bh);
                mma_bf16(acc[m][n], am[m], bh);
                mma_bf16(acc[m][n], ah[m], bm);
            }
        }
    }
}

// Build next-layer A fragments from accumulators (+bias, relu, hi/mid split).
// af[m][j][0..3] = hi regs, [4..7] = mid regs for k-chunk j.
__device__ __forceinline__ void build_frag(const float acc[2][8][4],
                                           const float* bias, int cg,
                                           uint32_t af[2][4][8])
{
#pragma unroll
    for (int m = 0; m < 2; m++) {
#pragma unroll
        for (int j = 0; j < 4; j++) {
            const float* a0 = acc[m][2 * j];
            const float* a1 = acc[m][2 * j + 1];
            float bA0 = bias[(2 * j) * 8 + 2 * cg],     bB0 = bias[(2 * j) * 8 + 2 * cg + 1];
            float bA1 = bias[(2 * j + 1) * 8 + 2 * cg], bB1 = bias[(2 * j + 1) * 8 + 2 * cg + 1];
            float x0 = fmaxf(a0[0] + bA0, 0.f), x1 = fmaxf(a0[1] + bB0, 0.f);
            float x2 = fmaxf(a0[2] + bA0, 0.f), x3 = fmaxf(a0[3] + bB0, 0.f);
            float x4 = fmaxf(a1[0] + bA1, 0.f), x5 = fmaxf(a1[1] + bB1, 0.f);
            float x6 = fmaxf(a1[2] + bA1, 0.f), x7 = fmaxf(a1[3] + bB1, 0.f);
            unsigned h0 = cvt2(x0, x1), h1 = cvt2(x2, x3);
            unsigned h2 = cvt2(x4, x5), h3 = cvt2(x6, x7);
            af[m][j][0] = h0; af[m][j][1] = h1; af[m][j][2] = h2; af[m][j][3] = h3;
            af[m][j][4] = mid2(x0, x1, h0); af[m][j][5] = mid2(x2, x3, h1);
            af[m][j][6] = mid2(x4, x5, h2); af[m][j][7] = mid2(x6, x7, h3);
        }
    }
}

// Layers 2/3: A from register fragments, B hi/mid via ldsm2.
__device__ __forceinline__ void run_layer_frag(const uint32_t af[2][4][8],
                                               uint32_t wHb, uint32_t wMb,
                                               float acc[2][8][4])
{
#pragma unroll
    for (int m = 0; m < 2; m++)
#pragma unroll
        for (int n = 0; n < 8; n++)
#pragma unroll
            for (int q = 0; q < 4; q++) acc[m][n][q] = 0.f;
#pragma unroll
    for (int k = 0; k < 4; k++) {
#pragma unroll
        for (int n = 0; n < 8; n++) {
            uint32_t bh[2], bm[2];
            ldsm2(bh, wHb + n * 8 * WSTR23 + k * 32);
            ldsm2(bm, wMb + n * 8 * WSTR23 + k * 32);
#pragma unroll
            for (int m = 0; m < 2; m++) {
                mma_bf16(acc[m][n], &af[m][k][0], bh);
                mma_bf16(acc[m][n], &af[m][k][4], bh);
                mma_bf16(acc[m][n], &af[m][k][0], bm);
            }
        }
    }
}

__device__ __forceinline__ void epi_max(float acc[2][8][4], const float* bias,
                                        float* outp, int nbase, int lane)
{
    const int cg = lane & 3;
#pragma unroll
    for (int n = 0; n < 8; n++) {
        int n0 = nbase + n * 8 + 2 * cg;
        float b0v = bias[n0], b1v = bias[n0 + 1];
        float v0 = fmaxf(fmaxf(acc[0][n][0] + b0v, 0.f), fmaxf(acc[0][n][2] + b0v, 0.f));
        v0 = fmaxf(v0, fmaxf(fmaxf(acc[1][n][0] + b0v, 0.f), fmaxf(acc[1][n][2] + b0v, 0.f)));
        float v1 = fmaxf(fmaxf(acc[0][n][1] + b1v, 0.f), fmaxf(acc[0][n][3] + b1v, 0.f));
        v1 = fmaxf(v1, fmaxf(fmaxf(acc[1][n][1] + b1v, 0.f), fmaxf(acc[1][n][3] + b1v, 0.f)));
#pragma unroll
        for (int o = 4; o <= 16; o <<= 1) {
            v0 = fmaxf(v0, __shfl_xor_sync(FULLM, v0, o));
            v1 = fmaxf(v1, __shfl_xor_sync(FULLM, v1, o));
        }
        if (lane < 4) { outp[n0] = v0; outp[n0 + 1] = v1; }
    }
}

__global__ __launch_bounds__(256) void mlp_kernel(
    const float* __restrict__ xyz, const float* __restrict__ pts,
    const float* __restrict__ w0, const float* __restrict__ b0,
    const float* __restrict__ w1, const float* __restrict__ b1,
    const float* __restrict__ w2, const float* __restrict__ b2,
    const float* __restrict__ new_xyz, float* __restrict__ new_points)
{
    extern __shared__ char smem[];
    const uint32_t sb = smem_u32(smem);
    const int tid = threadIdx.x, wid = tid >> 5, lane = tid & 31;

    float* b0s = (float*)(smem + SM_BIAS);
    float* b1s = b0s + 64;
    float* b2s = b1s + 64;
    if (tid < 64) { b0s[tid] = b0[tid]; b1s[tid] = b1[tid]; }
    if (tid < 128) b2s[tid] = b2[tid];

    for (int idx = tid; idx < 64 * 80; idx += 256) {
        int n = idx / 80, k = idx - n * 80;
        float w = (k < 67) ? w0[k * 64 + n] : 0.f;
        __nv_bfloat16 h = __float2bfloat16_rn(w);
        __nv_bfloat16 m = __float2bfloat16_rn(w - __bfloat162float(h));
        *(unsigned short*)(smem + SM_W1H + n * WSTR1 + k * 2) = __bfloat16_as_ushort(h);
        *(unsigned short*)(smem + SM_W1M + n * WSTR1 + k * 2) = __bfloat16_as_ushort(m);
    }
    for (int idx = tid; idx < 64 * 64; idx += 256) {
        int n = idx >> 6, k = idx & 63;
        float w = w1[k * 64 + n];
        __nv_bfloat16 h = __float2bfloat16_rn(w);
        __nv_bfloat16 m = __float2bfloat16_rn(w - __bfloat162float(h));
        *(unsigned short*)(smem + SM_W2H + n * WSTR23 + k * 2) = __bfloat16_as_ushort(h);
        *(unsigned short*)(smem + SM_W2M + n * WSTR23 + k * 2) = __bfloat16_as_ushort(m);
    }
    for (int idx = tid; idx < 128 * 64; idx += 256) {
        int n = idx >> 6, k = idx & 63;
        float w = w2[k * 128 + n];
        __nv_bfloat16 h = __float2bfloat16_rn(w);
        __nv_bfloat16 m = __float2bfloat16_rn(w - __bfloat162float(h));
        *(unsigned short*)(smem + SM_W3H + n * WSTR23 + k * 2) = __bfloat16_as_ushort(h);
        *(unsigned short*)(smem + SM_W3M + n * WSTR23 + k * 2) = __bfloat16_as_ushort(m);
    }
    __syncthreads();

    char* actHp = smem + SM_ACT + wid * ACTW;
    char* actMp = actHp + 5632;
    const uint32_t actH_u = sb + SM_ACT + wid * ACTW;
    const uint32_t actM_u = actH_u + 5632;
    const uint32_t aH = actH_u + (lane & 15) * ASTRIDE + (lane >> 4) * 16;
    const uint32_t aM = actM_u + (lane & 15) * ASTRIDE + (lane >> 4) * 16;
    const int bl = lane & 15;
    const uint32_t wl1 = (bl & 7) * WSTR1  + ((bl >> 3) & 1) * 16;
    const uint32_t wl2 = (bl & 7) * WSTR23 + ((bl >> 3) & 1) * 16;
    const uint32_t w1H = sb + SM_W1H + wl1, w1M = sb + SM_W1M + wl1;
    const uint32_t w2H = sb + SM_W2H + wl2, w2M = sb + SM_W2M + wl2;
    const uint32_t w3H = sb + SM_W3H + wl2, w3M = sb + SM_W3M + wl2;
    const int cg = lane & 3;

#pragma unroll 1
    for (int cc = 0; cc < 4; cc++) {
        const int centroid = blockIdx.x * 32 + wid * 4 + cc;
        const int b = centroid >> 10;
        const int nid = d_ball[(size_t)centroid * KNBR + lane];

        __syncwarp();
        {
            float arr[80];
            const float4* pr = (const float4*)(pts + ((size_t)b * NPTS + nid) * CIN);
#pragma unroll
            for (int q = 0; q < 16; q++) {
                float4 v = pr[q];
                arr[4 * q] = v.x; arr[4 * q + 1] = v.y; arr[4 * q + 2] = v.z; arr[4 * q + 3] = v.w;
            }
            const float* xr = xyz + ((size_t)b * NPTS + nid) * 3;
            const float* nc = new_xyz + (size_t)centroid * 3;
            arr[64] = __fsub_rn(xr[0], nc[0]);
            arr[65] = __fsub_rn(xr[1], nc[1]);
            arr[66] = __fsub_rn(xr[2], nc[2]);
#pragma unroll
            for (int i = 67; i < 80; i++) arr[i] = 0.f;

            uint32_t* rowH = (uint32_t*)(actHp + lane * ASTRIDE);
            uint32_t* rowM = (uint32_t*)(actMp + lane * ASTRIDE);
#pragma unroll
            for (int i = 0; i < 40; i++) {
                unsigned h = cvt2(arr[2 * i], arr[2 * i + 1]);
                rowH[i] = h;
                rowM[i] = mid2(arr[2 * i], arr[2 * i + 1], h);
            }
        }
        __syncwarp();

        float acc[2][8][4];
        run_layer1(aH, aM, w1H, w1M, acc);
        __syncwarp();                 // act smem free for next centroid's gather

        uint32_t af[2][4][8];
        build_frag(acc, b0s, cg, af); // L1 out -> L2 A fragments (registers)
        run_layer_frag(af, w2H, w2M, acc);
        build_frag(acc, b1s, cg, af); // L2 out -> L3 A fragments
        float* outp = new_points + (size_t)centroid * 128;
        run_layer_frag(af, w3H, w3M, acc);
        epi_max(acc, b2s, outp, 0, lane);
        run_layer_frag(af, w3H + 64 * WSTR23, w3M + 64 * WSTR23, acc);
        epi_max(acc, b2s, outp, 64, lane);
    }
}

// ---------------------------------------------------------------------------
extern "C" void kernel_launch(void* const* d_in, const int* in_sizes, int n_in,
                              void* d_out, int out_size)
{
    (void)in_sizes; (void)n_in; (void)out_size;
    const float* xyz = (const float*)d_in[0];
    const float* pts = (const float*)d_in[1];
    const float* w0  = (const float*)d_in[2];
    const float* b0  = (const float*)d_in[3];
    const float* w1  = (const float*)d_in[4];
    const float* b1  = (const float*)d_in[5];
    const float* w2  = (const float*)d_in[6];
    const float* b2  = (const float*)d_in[7];

    float* out      = (float*)d_out;
    float* new_xyz  = out;
    float* new_pts  = out + (size_t)BATCH * NSAMP * 3;

    const int FPS_SMEM = NPTS * 16 + 128;
    const int MLP_SMEM = SM_MLP_END;

    cudaFuncSetAttribute(fps_kernel, cudaFuncAttributeMaxDynamicSharedMemorySize, FPS_SMEM);
    cudaFuncSetAttribute(mlp_kernel, cudaFuncAttributeMaxDynamicSharedMemorySize, MLP_SMEM);

    fps_kernel<<<BATCH, 256, FPS_SMEM>>>(xyz, new_xyz);
    query_kernel<<<(BATCH * NSAMP) / 8, 256>>>(xyz, new_xyz);
    mlp_kernel<<<(BATCH * NSAMP) / 32, 256, MLP_SMEM>>>(
        xyz, pts, w0, b0, w1, b1, w2, b2, new_xyz, new_pts);
}

// round 10
// speedup vs baseline: 1.2712x; 1.0027x over previous
#include <cuda_runtime.h>
#include <cuda_bf16.h>
#include <cstdint>

#define BATCH 16
#define NPTS  4096
#define CIN   64
#define NSAMP 1024
#define KNBR  32
#define FULLM 0xffffffffu

// ---------------- f32x2 helpers (FPS only) ----------------
#define PACKF2(d, lo, hi)  asm("mov.b64 %0, {%1, %2};" : "=l"(d) : "f"(lo), "f"(hi))
#define UNPACKF2(lo, hi, s) asm("mov.b64 {%0, %1}, %2;" : "=f"(lo), "=f"(hi) : "l"(s))
#define ADD2(d, a, b) asm("add.rn.f32x2 %0, %1, %2;" : "=l"(d) : "l"(a), "l"(b))
#define MUL2(d, a, b) asm("mul.rn.f32x2 %0, %1, %2;" : "=l"(d) : "l"(a), "l"(b))

__device__ int d_ball[BATCH * NSAMP * KNBR];

#define AMAX(vA, jA, vB, jB, vO, jO) { bool g_ = ((vB) > (vA)); (vO) = g_ ? (vB) : (vA); (jO) = g_ ? (jB) : (jA); }

// ---------------------------------------------------------------------------
// Kernel 1: FPS (unchanged — 343us, bit-exact)
// ---------------------------------------------------------------------------
__global__ __launch_bounds__(256) void fps_kernel(const float* __restrict__ xyz,
                                                  float* __restrict__ new_xyz)
{
    extern __shared__ float sm[];
    float4* sxyz = (float4*)sm;
    unsigned long long* sred = (unsigned long long*)(sm + NPTS * 4);

    const int b = blockIdx.x, tid = threadIdx.x;
    const int lane = tid & 31, warp = tid >> 5;
    const float* gx = xyz + (size_t)b * NPTS * 3;

    for (int i = tid; i < NPTS; i += 256) {
        float4 v;
        v.x = gx[3 * i]; v.y = gx[3 * i + 1]; v.z = gx[3 * i + 2]; v.w = 0.f;
        sxyz[i] = v;
    }
    __syncthreads();

    unsigned long long px[8], py[8], pz[8];
    float dist[16];
#pragma unroll
    for (int q = 0; q < 8; q++) {
        float4 a = sxyz[tid + (2 * q) * 256];
        float4 c = sxyz[tid + (2 * q + 1) * 256];
        PACKF2(px[q], a.x, c.x);
        PACKF2(py[q], a.y, c.y);
        PACKF2(pz[q], a.z, c.z);
        dist[2 * q] = 1e10f; dist[2 * q + 1] = 1e10f;
    }

    int far = 0;
    for (int t = 0; t < NSAMP; t++) {
        float4 cen = sxyz[far];
        if (tid == 0) {
            float* o = new_xyz + ((size_t)b * NSAMP + t) * 3;
            o[0] = cen.x; o[1] = cen.y; o[2] = cen.z;
        }
        unsigned long long ncx, ncy, ncz;
        float mx = -cen.x, my = -cen.y, mz = -cen.z;
        PACKF2(ncx, mx, mx); PACKF2(ncy, my, my); PACKF2(ncz, mz, mz);

        float v[16];
#pragma unroll
        for (int q = 0; q < 8; q++) {
            unsigned long long dx, dy, dz, xx, yy, zz, s, d2;
            ADD2(dx, px[q], ncx);
            ADD2(dy, py[q], ncy);
            ADD2(dz, pz[q], ncz);
            MUL2(xx, dx, dx); MUL2(yy, dy, dy); MUL2(zz, dz, dz);
            ADD2(s, xx, yy); ADD2(d2, s, zz);
            float d0, d1;
            UNPACKF2(d0, d1, d2);
            float n0 = fminf(dist[2 * q], d0);     dist[2 * q] = n0;     v[2 * q] = n0;
            float n1 = fminf(dist[2 * q + 1], d1); dist[2 * q + 1] = n1; v[2 * q + 1] = n1;
        }
        float va[8]; int ja[8];
#pragma unroll
        for (int q = 0; q < 8; q++) AMAX(v[2 * q], 2 * q, v[2 * q + 1], 2 * q + 1, va[q], ja[q]);
        float vb[4]; int jb[4];
#pragma unroll
        for (int q = 0; q < 4; q++) AMAX(va[2 * q], ja[2 * q], va[2 * q + 1], ja[2 * q + 1], vb[q], jb[q]);
        float vc0, vc1; int jc0, jc1;
        AMAX(vb[0], jb[0], vb[1], jb[1], vc0, jc0);
        AMAX(vb[2], jb[2], vb[3], jb[3], vc1, jc1);
        float mv; int mj;
        AMAX(vc0, jc0, vc1, jc1, mv, mj);
        int bi = tid + mj * 256;

        unsigned bits = __float_as_uint(mv);
        unsigned wmax = __reduce_max_sync(FULLM, bits);
        unsigned cand = (bits == wmax) ? (unsigned)(4095 - bi) : 0u;
        unsigned winv = __reduce_max_sync(FULLM, cand);

        const int pt = t & 1;
        if (lane == 0)
            sred[pt * 8 + warp] = ((unsigned long long)wmax << 32) | winv;
        __syncthreads();
        const ulonglong2* kr = (const ulonglong2*)(sred + pt * 8);
        ulonglong2 k0 = kr[0], k1 = kr[1], k2 = kr[2], k3 = kr[3];
        unsigned long long m0 = k0.x > k0.y ? k0.x : k0.y;
        unsigned long long m1 = k1.x > k1.y ? k1.x : k1.y;
        unsigned long long m2 = k2.x > k2.y ? k2.x : k2.y;
        unsigned long long m3 = k3.x > k3.y ? k3.x : k3.y;
        unsigned long long ma = m0 > m1 ? m0 : m1;
        unsigned long long mb = m2 > m3 ? m2 : m3;
        unsigned long long mm = ma > mb ? ma : mb;
        far = 4095 - (int)(unsigned)(mm & 0xffffffffull);
    }
}

// ---------------------------------------------------------------------------
// Kernel 2: ball query (unchanged)
// ---------------------------------------------------------------------------
__global__ __launch_bounds__(256) void query_kernel(const float* __restrict__ xyz,
                                                    const float* __restrict__ new_xyz)
{
    const int warp = threadIdx.x >> 5, lane = threadIdx.x & 31;
    const int gs = blockIdx.x * 8 + warp;
    const int b  = gs >> 10;
    const float* nc = new_xyz + (size_t)gs * 3;
    const float cx = nc[0], cy = nc[1], cz = nc[2];
    const float* gx = xyz + (size_t)b * NPTS * 3;
    int* out = d_ball + (size_t)gs * KNBR;
    const float R2 = 0.04f;

    int cnt = 0, first = -1;
    for (int base = 0; base < NPTS && cnt < KNBR; base += 32) {
        int j = base + lane;
        float dx = __fsub_rn(cx, gx[3 * j]);
        float dy = __fsub_rn(cy, gx[3 * j + 1]);
        float dz = __fsub_rn(cz, gx[3 * j + 2]);
        float d2 = __fadd_rn(__fadd_rn(__fmul_rn(dx, dx), __fmul_rn(dy, dy)),
                             __fmul_rn(dz, dz));
        bool in = (d2 <= R2);
        unsigned m = __ballot_sync(FULLM, in);
        int pos = cnt + __popc(m & ((1u << lane) - 1u));
        if (in && pos < KNBR) {
            out[pos] = j;
            if (pos == 0) first = j;
        }
        cnt += __popc(m);
    }
    unsigned hf = __ballot_sync(FULLM, first >= 0);
    int src = __ffs(hf) - 1;
    first = __shfl_sync(FULLM, first, src);
    int filled = cnt < KNBR ? cnt : KNBR;
    if (lane >= filled) out[lane] = first;
}

// ---------------------------------------------------------------------------
// Kernel 3: MLP via mma.sync. Reordered mainloops: per k-chunk, load all B
// fragments, then issue term-major mma sweeps — consecutive mmas hit
// different accumulators (16 independent between reuses). Per-acc
// accumulation order unchanged -> bit-identical to R9.
// ---------------------------------------------------------------------------
#define ASTRIDE  176
#define WSTR1    176
#define WSTR23   144
#define SM_BIAS  0
#define SM_W1H   1024
#define SM_W1M   12288
#define SM_W2H   23552
#define SM_W2M   32768
#define SM_W3H   41984
#define SM_W3M   60416
#define SM_ACT   78848
#define ACTW     11264
#define SM_MLP_END (78848 + 8 * ACTW)   // 168960

__device__ __forceinline__ unsigned cvt2(float lo, float hi) {
    unsigned r;
    asm("cvt.rn.bf16x2.f32 %0, %1, %2;" : "=r"(r) : "f"(hi), "f"(lo));
    return r;
}
__device__ __forceinline__ unsigned mid2(float lo, float hi, unsigned h2) {
    float lh = __uint_as_float(h2 << 16);
    float hh = __uint_as_float(h2 & 0xffff0000u);
    return cvt2(lo - lh, hi - hh);
}
__device__ __forceinline__ uint32_t smem_u32(const void* p) {
    uint32_t a;
    asm("{ .reg .u64 t; cvta.to.shared.u64 t, %1; cvt.u32.u64 %0, t; }" : "=r"(a) : "l"(p));
    return a;
}
__device__ __forceinline__ void ldsm4(uint32_t* r, uint32_t addr) {
    asm volatile("ldmatrix.sync.aligned.m8n8.x4.shared.b16 {%0,%1,%2,%3}, [%4];"
        : "=r"(r[0]), "=r"(r[1]), "=r"(r[2]), "=r"(r[3]) : "r"(addr));
}
__device__ __forceinline__ void ldsm2(uint32_t* r, uint32_t addr) {
    asm volatile("ldmatrix.sync.aligned.m8n8.x2.shared.b16 {%0,%1}, [%2];"
        : "=r"(r[0]), "=r"(r[1]) : "r"(addr));
}
__device__ __forceinline__ void mma_bf16(float* d, const uint32_t* a, const uint32_t* b) {
    asm volatile("mma.sync.aligned.m16n8k16.row.col.f32.bf16.bf16.f32 "
        "{%0,%1,%2,%3}, {%4,%5,%6,%7}, {%8,%9}, {%0,%1,%2,%3};"
        : "+f"(d[0]), "+f"(d[1]), "+f"(d[2]), "+f"(d[3])
        : "r"(a[0]), "r"(a[1]), "r"(a[2]), "r"(a[3]), "r"(b[0]), "r"(b[1]));
}

// Layer 1: A hi/mid from smem via ldmatrix; per k: load all B, term-major mmas.
__device__ __forceinline__ void run_layer1(uint32_t aH, uint32_t aM,
                                           uint32_t wHb, uint32_t wMb,
                                           float acc[2][8][4])
{
#pragma unroll
    for (int m = 0; m < 2; m++)
#pragma unroll
        for (int n = 0; n < 8; n++)
#pragma unroll
            for (int q = 0; q < 4; q++) acc[m][n][q] = 0.f;
#pragma unroll
    for (int k = 0; k < 5; k++) {
        uint32_t ah[2][4], am[2][4];
        ldsm4(ah[0], aH + k * 32);
        ldsm4(ah[1], aH + 16 * ASTRIDE + k * 32);
        ldsm4(am[0], aM + k * 32);
        ldsm4(am[1], aM + 16 * ASTRIDE + k * 32);
        uint32_t bh[8][2], bm[8][2];
#pragma unroll
        for (int n = 0; n < 8; n++) {
            ldsm2(bh[n], wHb + n * 8 * WSTR1 + k * 32);
            ldsm2(bm[n], wMb + n * 8 * WSTR1 + k * 32);
        }
#pragma unroll
        for (int n = 0; n < 8; n++)
#pragma unroll
            for (int m = 0; m < 2; m++)
                mma_bf16(acc[m][n], ah[m], bh[n]);
#pragma unroll
        for (int n = 0; n < 8; n++)
#pragma unroll
            for (int m = 0; m < 2; m++)
                mma_bf16(acc[m][n], am[m], bh[n]);
#pragma unroll
        for (int n = 0; n < 8; n++)
#pragma unroll
            for (int m = 0; m < 2; m++)
                mma_bf16(acc[m][n], ah[m], bm[n]);
    }
}

// Build next-layer A fragments from accumulators (+bias, relu, hi/mid split).
__device__ __forceinline__ void build_frag(const float acc[2][8][4],
                                           const float* bias, int cg,
                                           uint32_t af[2][4][8])
{
#pragma unroll
    for (int m = 0; m < 2; m++) {
#pragma unroll
        for (int j = 0; j < 4; j++) {
            const float* a0 = acc[m][2 * j];
            const float* a1 = acc[m][2 * j + 1];
            float bA0 = bias[(2 * j) * 8 + 2 * cg],     bB0 = bias[(2 * j) * 8 + 2 * cg + 1];
            float bA1 = bias[(2 * j + 1) * 8 + 2 * cg], bB1 = bias[(2 * j + 1) * 8 + 2 * cg + 1];
            float x0 = fmaxf(a0[0] + bA0, 0.f), x1 = fmaxf(a0[1] + bB0, 0.f);
            float x2 = fmaxf(a0[2] + bA0, 0.f), x3 = fmaxf(a0[3] + bB0, 0.f);
            float x4 = fmaxf(a1[0] + bA1, 0.f), x5 = fmaxf(a1[1] + bB1, 0.f);
            float x6 = fmaxf(a1[2] + bA1, 0.f), x7 = fmaxf(a1[3] + bB1, 0.f);
            unsigned h0 = cvt2(x0, x1), h1 = cvt2(x2, x3);
            unsigned h2 = cvt2(x4, x5), h3 = cvt2(x6, x7);
            af[m][j][0] = h0; af[m][j][1] = h1; af[m][j][2] = h2; af[m][j][3] = h3;
            af[m][j][4] = mid2(x0, x1, h0); af[m][j][5] = mid2(x2, x3, h1);
            af[m][j][6] = mid2(x4, x5, h2); af[m][j][7] = mid2(x6, x7, h3);
        }
    }
}

// Layers 2/3: A from register fragments; per k: load all B, term-major mmas.
__device__ __forceinline__ void run_layer_frag(const uint32_t af[2][4][8],
                                               uint32_t wHb, uint32_t wMb,
                                               float acc[2][8][4])
{
#pragma unroll
    for (int m = 0; m < 2; m++)
#pragma unroll
        for (int n = 0; n < 8; n++)
#pragma unroll
            for (int q = 0; q < 4; q++) acc[m][n][q] = 0.f;
#pragma unroll
    for (int k = 0; k < 4; k++) {
        uint32_t bh[8][2], bm[8][2];
#pragma unroll
        for (int n = 0; n < 8; n++) {
            ldsm2(bh[n], wHb + n * 8 * WSTR23 + k * 32);
            ldsm2(bm[n], wMb + n * 8 * WSTR23 + k * 32);
        }
#pragma unroll
        for (int n = 0; n < 8; n++)
#pragma unroll
            for (int m = 0; m < 2; m++)
                mma_bf16(acc[m][n], &af[m][k][0], bh[n]);
#pragma unroll
        for (int n = 0; n < 8; n++)
#pragma unroll
            for (int m = 0; m < 2; m++)
                mma_bf16(acc[m][n], &af[m][k][4], bh[n]);
#pragma unroll
        for (int n = 0; n < 8; n++)
#pragma unroll
            for (int m = 0; m < 2; m++)
                mma_bf16(acc[m][n], &af[m][k][0], bm[n]);
    }
}

__device__ __forceinline__ void epi_max(float acc[2][8][4], const float* bias,
                                        float* outp, int nbase, int lane)
{
    const int cg = lane & 3;
#pragma unroll
    for (int n = 0; n < 8; n++) {
        int n0 = nbase + n * 8 + 2 * cg;
        float b0v = bias[n0], b1v = bias[n0 + 1];
        float v0 = fmaxf(fmaxf(acc[0][n][0] + b0v, 0.f), fmaxf(acc[0][n][2] + b0v, 0.f));
        v0 = fmaxf(v0, fmaxf(fmaxf(acc[1][n][0] + b0v, 0.f), fmaxf(acc[1][n][2] + b0v, 0.f)));
        float v1 = fmaxf(fmaxf(acc[0][n][1] + b1v, 0.f), fmaxf(acc[0][n][3] + b1v, 0.f));
        v1 = fmaxf(v1, fmaxf(fmaxf(acc[1][n][1] + b1v, 0.f), fmaxf(acc[1][n][3] + b1v, 0.f)));
#pragma unroll
        for (int o = 4; o <= 16; o <<= 1) {
            v0 = fmaxf(v0, __shfl_xor_sync(FULLM, v0, o));
            v1 = fmaxf(v1, __shfl_xor_sync(FULLM, v1, o));
        }
        if (lane < 4) { outp[n0] = v0; outp[n0 + 1] = v1; }
    }
}

__global__ __launch_bounds__(256) void mlp_kernel(
    const float* __restrict__ xyz, const float* __restrict__ pts,
    const float* __restrict__ w0, const float* __restrict__ b0,
    const float* __restrict__ w1, const float* __restrict__ b1,
    const float* __restrict__ w2, const float* __restrict__ b2,
    const float* __restrict__ new_xyz, float* __restrict__ new_points)
{
    extern __shared__ char smem[];
    const uint32_t sb = smem_u32(smem);
    const int tid = threadIdx.x, wid = tid >> 5, lane = tid & 31;

    float* b0s = (float*)(smem + SM_BIAS);
    float* b1s = b0s + 64;
    float* b2s = b1s + 64;
    if (tid < 64) { b0s[tid] = b0[tid]; b1s[tid] = b1[tid]; }
    if (tid < 128) b2s[tid] = b2[tid];

    for (int idx = tid; idx < 64 * 80; idx += 256) {
        int n = idx / 80, k = idx - n * 80;
        float w = (k < 67) ? w0[k * 64 + n] : 0.f;
        __nv_bfloat16 h = __float2bfloat16_rn(w);
        __nv_bfloat16 m = __float2bfloat16_rn(w - __bfloat162float(h));
        *(unsigned short*)(smem + SM_W1H + n * WSTR1 + k * 2) = __bfloat16_as_ushort(h);
        *(unsigned short*)(smem + SM_W1M + n * WSTR1 + k * 2) = __bfloat16_as_ushort(m);
    }
    for (int idx = tid; idx < 64 * 64; idx += 256) {
        int n = idx >> 6, k = idx & 63;
        float w = w1[k * 64 + n];
        __nv_bfloat16 h = __float2bfloat16_rn(w);
        __nv_bfloat16 m = __float2bfloat16_rn(w - __bfloat162float(h));
        *(unsigned short*)(smem + SM_W2H + n * WSTR23 + k * 2) = __bfloat16_as_ushort(h);
        *(unsigned short*)(smem + SM_W2M + n * WSTR23 + k * 2) = __bfloat16_as_ushort(m);
    }
    for (int idx = tid; idx < 128 * 64; idx += 256) {
        int n = idx >> 6, k = idx & 63;
        float w = w2[k * 128 + n];
        __nv_bfloat16 h = __float2bfloat16_rn(w);
        __nv_bfloat16 m = __float2bfloat16_rn(w - __bfloat162float(h));
        *(unsigned short*)(smem + SM_W3H + n * WSTR23 + k * 2) = __bfloat16_as_ushort(h);
        *(unsigned short*)(smem + SM_W3M + n * WSTR23 + k * 2) = __bfloat16_as_ushort(m);
    }
    __syncthreads();

    char* actHp = smem + SM_ACT + wid * ACTW;
    char* actMp = actHp + 5632;
    const uint32_t actH_u = sb + SM_ACT + wid * ACTW;
    const uint32_t actM_u = actH_u + 5632;
    const uint32_t aH = actH_u + (lane & 15) * ASTRIDE + (lane >> 4) * 16;
    const uint32_t aM = actM_u + (lane & 15) * ASTRIDE + (lane >> 4) * 16;
    const int bl = lane & 15;
    const uint32_t wl1 = (bl & 7) * WSTR1  + ((bl >> 3) & 1) * 16;
    const uint32_t wl2 = (bl & 7) * WSTR23 + ((bl >> 3) & 1) * 16;
    const uint32_t w1H = sb + SM_W1H + wl1, w1M = sb + SM_W1M + wl1;
    const uint32_t w2H = sb + SM_W2H + wl2, w2M = sb + SM_W2M + wl2;
    const uint32_t w3H = sb + SM_W3H + wl2, w3M = sb + SM_W3M + wl2;
    const int cg = lane & 3;

#pragma unroll 1
    for (int cc = 0; cc < 4; cc++) {
        const int centroid = blockIdx.x * 32 + wid * 4 + cc;
        const int b = centroid >> 10;
        const int nid = d_ball[(size_t)centroid * KNBR + lane];

        __syncwarp();
        {
            float arr[80];
            const float4* pr = (const float4*)(pts + ((size_t)b * NPTS + nid) * CIN);
#pragma unroll
            for (int q = 0; q < 16; q++) {
                float4 v = pr[q];
                arr[4 * q] = v.x; arr[4 * q + 1] = v.y; arr[4 * q + 2] = v.z; arr[4 * q + 3] = v.w;
            }
            const float* xr = xyz + ((size_t)b * NPTS + nid) * 3;
            const float* nc = new_xyz + (size_t)centroid * 3;
            arr[64] = __fsub_rn(xr[0], nc[0]);
            arr[65] = __fsub_rn(xr[1], nc[1]);
            arr[66] = __fsub_rn(xr[2], nc[2]);
#pragma unroll
            for (int i = 67; i < 80; i++) arr[i] = 0.f;

            uint32_t* rowH = (uint32_t*)(actHp + lane * ASTRIDE);
            uint32_t* rowM = (uint32_t*)(actMp + lane * ASTRIDE);
#pragma unroll
            for (int i = 0; i < 40; i++) {
                unsigned h = cvt2(arr[2 * i], arr[2 * i + 1]);
                rowH[i] = h;
                rowM[i] = mid2(arr[2 * i], arr[2 * i + 1], h);
            }
        }
        __syncwarp();

        float acc[2][8][4];
        run_layer1(aH, aM, w1H, w1M, acc);
        __syncwarp();

        uint32_t af[2][4][8];
        build_frag(acc, b0s, cg, af);
        run_layer_frag(af, w2H, w2M, acc);
        build_frag(acc, b1s, cg, af);
        float* outp = new_points + (size_t)centroid * 128;
        run_layer_frag(af, w3H, w3M, acc);
        epi_max(acc, b2s, outp, 0, lane);
        run_layer_frag(af, w3H + 64 * WSTR23, w3M + 64 * WSTR23, acc);
        epi_max(acc, b2s, outp, 64, lane);
    }
}

// ---------------------------------------------------------------------------
extern "C" void kernel_launch(void* const* d_in, const int* in_sizes, int n_in,
                              void* d_out, int out_size)
{
    (void)in_sizes; (void)n_in; (void)out_size;
    const float* xyz = (const float*)d_in[0];
    const float* pts = (const float*)d_in[1];
    const float* w0  = (const float*)d_in[2];
    const float* b0  = (const float*)d_in[3];
    const float* w1  = (const float*)d_in[4];
    const float* b1  = (const float*)d_in[5];
    const float* w2  = (const float*)d_in[6];
    const float* b2  = (const float*)d_in[7];

    float* out      = (float*)d_out;
    float* new_xyz  = out;
    float* new_pts  = out + (size_t)BATCH * NSAMP * 3;

    const int FPS_SMEM = NPTS * 16 + 128;
    const int MLP_SMEM = SM_MLP_END;

    cudaFuncSetAttribute(fps_kernel, cudaFuncAttributeMaxDynamicSharedMemorySize, FPS_SMEM);
    cudaFuncSetAttribute(mlp_kernel, cudaFuncAttributeMaxDynamicSharedMemorySize, MLP_SMEM);

    fps_kernel<<<BATCH, 256, FPS_SMEM>>>(xyz, new_xyz);
    query_kernel<<<(BATCH * NSAMP) / 8, 256>>>(xyz, new_xyz);
    mlp_kernel<<<(BATCH * NSAMP) / 32, 256, MLP_SMEM>>>(
        xyz, pts, w0, b0, w1, b1, w2, b2, new_xyz, new_pts);
}